// round 12
// baseline (speedup 1.0000x reference)
#include <cuda_runtime.h>
#include <math.h>

#define NBATCH   128
#define N_ATOMS  4096
#define NB       4095
#define NA       4094
#define NT       4093
#define MAX_LEN  (5 * NT)            /* 20465 rows */
#define ROW      9
#define TOT_F    (MAX_LEN * ROW)     /* 184185 floats per sample */
#define EPS      1e-8f

/* ---------------- scratch (static device globals; allocation-free) -------- */
#define CSTRIDE  16384               /* floats per sample: 4096 atoms x 4    */
#define BSTRIDE  12288               /* u16 per sample (3*NB = 12285)        */
#define ASTRIDE  16384               /* u16 per sample (4*NA = 16376)        */
#define TSTRIDE  20480               /* u16 per sample (5*NT = 20465)        */

__device__ float          g_coords[NBATCH * CSTRIDE];
__device__ unsigned short g_bonds [NBATCH * BSTRIDE];
__device__ unsigned short g_angs  [NBATCH * ASTRIDE];
__device__ unsigned short g_tors  [NBATCH * TSTRIDE];

/* ================= Kernel A: streaming extraction + output zeroing ======== */
#define A_THREADS   256
#define A_TILE_ROWS 512
#define A_TILES     40               /* ceil(20465/512) */
#define A_TILE_F    (A_TILE_ROWS * ROW)  /* 4608 */
#define A_BUF_F     (A_TILE_F + 8)

__global__ __launch_bounds__(A_THREADS)
void extract_kernel(const float* __restrict__ feats, float* __restrict__ out)
{
    __shared__ float stg[A_BUF_F];

    const int blk = blockIdx.x;
    const int b   = blk / A_TILES;
    const int t   = blk - b * A_TILES;
    const int tid = threadIdx.x;

    if (t == 0 && tid < 3) out[3 * b + tid] = 0.0f;

    const size_t gbase = (size_t)b * TOT_F + (size_t)t * A_TILE_F;
    const int    aoff  = (int)(gbase & 3);
    const float* abase = feats + (gbase - aoff);   /* 16B aligned */

    int rows = MAX_LEN - t * A_TILE_ROWS;
    if (rows > A_TILE_ROWS) rows = A_TILE_ROWS;
    int nv4 = (rows * ROW + aoff + 3) >> 2;
    const size_t total_f = (size_t)NBATCH * TOT_F;
    int cap = (int)((total_f - (gbase - aoff)) >> 2);
    if (nv4 > cap) nv4 = cap;

    {
        const float4* src = (const float4*)abase;
        float4*       dst = (float4*)stg;
        for (int j = tid; j < nv4; j += A_THREADS)
            dst[j] = src[j];
    }
    __syncthreads();

    float*          cb = g_coords + (size_t)b * CSTRIDE;
    unsigned short* bb = g_bonds  + (size_t)b * BSTRIDE;
    unsigned short* ab = g_angs   + (size_t)b * ASTRIDE;
    unsigned short* tb = g_tors   + (size_t)b * TSTRIDE;

    #pragma unroll
    for (int k = 0; k < A_TILE_ROWS / A_THREADS; k++) {
        int rl = tid + k * A_THREADS;
        int r  = t * A_TILE_ROWS + rl;
        if (rl < rows) {
            int base = ROW * rl + aoff;
            float c5 = stg[base + 5];
            float c6 = stg[base + 6];
            float c7 = stg[base + 7];
            float c8 = stg[base + 8];
            if (r < 3 * N_ATOMS) {
                int a    = r / 3;
                int comp = r - 3 * a;
                cb[4 * a + comp] = c5;
            }
            if (r < 3 * NB) bb[r] = (unsigned short)(int)c6;
            if (r < 4 * NA) ab[r] = (unsigned short)(int)c7;
            tb[r] = (unsigned short)(int)c8;
        }
    }
}

/* ================= Kernel B: compute (2 CTAs/sample, float4, ILP-2) ======= */
#define B_THREADS 512
#define B_SPLIT   2

/* tables after coords: float2 bond[15], float2 angle[13], float4 tor[25], red */
#define TB_BOND_F  (4 * N_ATOMS)               /* float idx of bond table  */
#define TB_ANG_F   (TB_BOND_F + 32)            /* 15 float2 -> 30, pad 32  */
#define TB_TOR_F   (TB_ANG_F + 28)             /* 13 float2 -> 26, pad 28  */
#define TB_RED_F   (TB_TOR_F + 100)            /* 25 float4 = 100          */
#define B_SMEM     ((TB_RED_F + 48) * 4)

__global__ __launch_bounds__(B_THREADS)
void energy_kernel(const float* __restrict__ bond_type,
                   const float* __restrict__ angle_type,
                   const float* __restrict__ tor_type,
                   const int*   __restrict__ multiplicity,
                   const float* __restrict__ opt_pars,
                   float* __restrict__ out)
{
    extern __shared__ float smem[];
    float4* sc4  = (float4*)smem;
    float2* sbt2 = (float2*)(smem + TB_BOND_F);
    float2* sat2 = (float2*)(smem + TB_ANG_F);
    float4* stt4 = (float4*)(smem + TB_TOR_F);
    float*  sred = smem + TB_RED_F;

    const int blk  = blockIdx.x;
    const int b    = blk >> 1;
    const int part = blk & 1;
    const int tid  = threadIdx.x;

    /* tables (packed) */
    if (tid < 15) sbt2[tid] = make_float2(bond_type[2 * tid], bond_type[2 * tid + 1]);
    else if (tid < 28) {
        int t = tid - 15;
        sat2[t] = make_float2(angle_type[2 * t], angle_type[2 * t + 1]);
    } else if (tid < 53) {
        int t = tid - 28;
        float p = tor_type[2 * t + 1];
        stt4[t] = make_float4(tor_type[2 * t], cosf(p), sinf(p), (float)multiplicity[t]);
    }

    /* coords: coalesced float4 copy (8 per thread) */
    {
        const float4* src = (const float4*)(g_coords + (size_t)b * CSTRIDE);
        #pragma unroll
        for (int k = 0; k < N_ATOMS / B_THREADS; k++)
            sc4[tid + k * B_THREADS] = src[tid + k * B_THREADS];
    }
    __syncthreads();

    const unsigned short* bb = g_bonds + (size_t)b * BSTRIDE;
    const unsigned short* ab = g_angs  + (size_t)b * ASTRIDE;
    const unsigned short* tb = g_tors  + (size_t)b * TSTRIDE;

    float eb = 0.0f, ea = 0.0f, et = 0.0f;

    /* ---------------- bonds (pairs, indices batched) ---------------- */
    {
        int e0 = (NB * part) / B_SPLIT;
        int e1 = (NB * (part + 1)) / B_SPLIT;
        for (int e = e0 + tid; e < e1; e += 2 * B_THREADS) {
            int eA = e;
            int eB = e + B_THREADS;
            bool hB = eB < e1;
            int eBs = hB ? eB : eA;
            int i0A = bb[3 * eA + 0], i1A = bb[3 * eA + 1], tyA = bb[3 * eA + 2];
            int i0B = bb[3 * eBs + 0], i1B = bb[3 * eBs + 1], tyB = bb[3 * eBs + 2];

            float4 p0A = sc4[i0A], p1A = sc4[i1A];
            float4 p0B = sc4[i0B], p1B = sc4[i1B];
            float2 btA = sbt2[tyA], btB = sbt2[tyB];

            float dxA = p0A.x - p1A.x, dyA = p0A.y - p1A.y, dzA = p0A.z - p1A.z;
            float rA  = sqrtf(dxA * dxA + dyA * dyA + dzA * dzA + EPS);
            float drA = rA - btA.y;
            eb += btA.x * drA * drA;

            float dxB = p0B.x - p1B.x, dyB = p0B.y - p1B.y, dzB = p0B.z - p1B.z;
            float rB  = sqrtf(dxB * dxB + dyB * dyB + dzB * dzB + EPS);
            float drB = rB - btB.y;
            eb += hB ? (btB.x * drB * drB) : 0.0f;
        }
    }

    /* ---------------- angles (pairs) ---------------- */
    {
        int e0 = (NA * part) / B_SPLIT;
        int e1 = (NA * (part + 1)) / B_SPLIT;
        for (int e = e0 + tid; e < e1; e += 2 * B_THREADS) {
            int eA = e;
            int eB = e + B_THREADS;
            bool hB = eB < e1;
            int eBs = hB ? eB : eA;
            int a0A = ab[4 * eA + 0], a1A = ab[4 * eA + 1], a2A = ab[4 * eA + 2], tyA = ab[4 * eA + 3];
            int a0B = ab[4 * eBs + 0], a1B = ab[4 * eBs + 1], a2B = ab[4 * eBs + 2], tyB = ab[4 * eBs + 3];

            float4 p0A = sc4[a0A], p1A = sc4[a1A], p2A = sc4[a2A];
            float4 p0B = sc4[a0B], p1B = sc4[a1B], p2B = sc4[a2B];
            float2 atA = sat2[tyA], atB = sat2[tyB];

            {
                float v1x = p0A.x - p1A.x, v1y = p0A.y - p1A.y, v1z = p0A.z - p1A.z;
                float v2x = p2A.x - p1A.x, v2y = p2A.y - p1A.y, v2z = p2A.z - p1A.z;
                float d11 = v1x * v1x + v1y * v1y + v1z * v1z + EPS;
                float d22 = v2x * v2x + v2y * v2y + v2z * v2z + EPS;
                float d12 = v1x * v2x + v1y * v2y + v1z * v2z;
                float cosang = d12 * rsqrtf(d11 * d22);
                cosang = fminf(fmaxf(cosang, -1.0f + 1e-6f), 1.0f - 1e-6f);
                float dt = acosf(cosang) - atA.y;
                ea += atA.x * dt * dt;
            }
            {
                float v1x = p0B.x - p1B.x, v1y = p0B.y - p1B.y, v1z = p0B.z - p1B.z;
                float v2x = p2B.x - p1B.x, v2y = p2B.y - p1B.y, v2z = p2B.z - p1B.z;
                float d11 = v1x * v1x + v1y * v1y + v1z * v1z + EPS;
                float d22 = v2x * v2x + v2y * v2y + v2z * v2z + EPS;
                float d12 = v1x * v2x + v1y * v2y + v1z * v2z;
                float cosang = d12 * rsqrtf(d11 * d22);
                cosang = fminf(fmaxf(cosang, -1.0f + 1e-6f), 1.0f - 1e-6f);
                float dt = acosf(cosang) - atB.y;
                ea += hB ? (atB.x * dt * dt) : 0.0f;
            }
        }
    }

    /* ---------------- torsions (pairs, analytic cos(n*phi - p)) ------------ */
    {
        int e0 = (NT * part) / B_SPLIT;
        int e1 = (NT * (part + 1)) / B_SPLIT;
        for (int e = e0 + tid; e < e1; e += 2 * B_THREADS) {
            int eA = e;
            int eB = e + B_THREADS;
            bool hB = eB < e1;
            int eBs = hB ? eB : eA;
            int tiA = tb[5 * eA + 0], tjA = tb[5 * eA + 1], tkA = tb[5 * eA + 2],
                tlA = tb[5 * eA + 3], tyA = tb[5 * eA + 4];
            int tiB = tb[5 * eBs + 0], tjB = tb[5 * eBs + 1], tkB = tb[5 * eBs + 2],
                tlB = tb[5 * eBs + 3], tyB = tb[5 * eBs + 4];

            float4 piA = sc4[tiA], pjA = sc4[tjA], pkA = sc4[tkA], plA = sc4[tlA];
            float4 piB = sc4[tiB], pjB = sc4[tjB], pkB = sc4[tkB], plB = sc4[tlB];
            float4 ttA = stt4[tyA], ttB = stt4[tyB];

            #pragma unroll
            for (int u = 0; u < 2; u++) {
                float4 pi = u ? piB : piA;
                float4 pj = u ? pjB : pjA;
                float4 pk = u ? pkB : pkA;
                float4 pl = u ? plB : plA;
                float4 tt = u ? ttB : ttA;

                float b1x = pj.x - pi.x, b1y = pj.y - pi.y, b1z = pj.z - pi.z;
                float b2x = pk.x - pj.x, b2y = pk.y - pj.y, b2z = pk.z - pj.z;
                float b3x = pl.x - pk.x, b3y = pl.y - pk.y, b3z = pl.z - pk.z;

                float n1x = b1y * b2z - b1z * b2y;
                float n1y = b1z * b2x - b1x * b2z;
                float n1z = b1x * b2y - b1y * b2x;
                float n2x = b2y * b3z - b2z * b3y;
                float n2y = b2z * b3x - b2x * b3z;
                float n2z = b2x * b3y - b2y * b3x;

                float L2 = b2x * b2x + b2y * b2y + b2z * b2z + EPS;
                float x  = n1x * n2x + n1y * n2y + n1z * n2z;

                float mx = n1y * b2z - n1z * b2y;
                float my = n1z * b2x - n1x * b2z;
                float mz = n1x * b2y - n1y * b2x;
                float ym = mx * n2x + my * n2y + mz * n2z;

                float uu  = x * x * L2 + ym * ym;
                float inv = rsqrtf(fmaxf(uu, 1e-38f));
                float L   = sqrtf(L2);
                float c   = x * L * inv;
                float s   = ym * inv;

                float cn = c, sn = s;
                if (tt.w > 1.5f) {
                    cn = 2.0f * c * c - 1.0f;
                    sn = 2.0f * s * c;
                }
                if (tt.w > 2.5f) {
                    float c3 = cn * c - sn * s;
                    float s3 = sn * c + cn * s;
                    cn = c3; sn = s3;
                }
                float val = tt.x * (1.0f + cn * tt.y + sn * tt.z);
                et += (u && !hB) ? 0.0f : val;
            }
        }
    }

    /* reduction (16 warps) + atomic accumulate */
    const unsigned FULL = 0xFFFFFFFFu;
    #pragma unroll
    for (int off = 16; off > 0; off >>= 1) {
        eb += __shfl_down_sync(FULL, eb, off);
        ea += __shfl_down_sync(FULL, ea, off);
        et += __shfl_down_sync(FULL, et, off);
    }
    int warp = tid >> 5;
    int lane = tid & 31;
    if (lane == 0) {
        sred[warp]      = eb;
        sred[16 + warp] = ea;
        sred[32 + warp] = et;
    }
    __syncthreads();
    if (warp == 0 && lane < 16) {
        float vb = sred[lane];
        float va = sred[16 + lane];
        float vt = sred[32 + lane];
        #pragma unroll
        for (int off = 8; off > 0; off >>= 1) {
            vb += __shfl_down_sync(0xFFFFu, vb, off);
            va += __shfl_down_sync(0xFFFFu, va, off);
            vt += __shfl_down_sync(0xFFFFu, vt, off);
        }
        if (lane == 0) {
            atomicAdd(&out[3 * b + 0], opt_pars[0] * vb);
            atomicAdd(&out[3 * b + 1], opt_pars[1] * va);
            atomicAdd(&out[3 * b + 2], opt_pars[2] * vt);
        }
    }
}

extern "C" void kernel_launch(void* const* d_in, const int* in_sizes, int n_in,
                              void* d_out, int out_size)
{
    const float* feats      = (const float*)d_in[0];
    /* d_in[1] = lengths (unused by reference) */
    const float* bond_type  = (const float*)d_in[2];
    const float* angle_type = (const float*)d_in[3];
    const float* tor_type   = (const float*)d_in[4];
    const int*   mult       = (const int*)  d_in[5];
    const float* opt_pars   = (const float*)d_in[6];
    float*       out        = (float*)d_out;

    extract_kernel<<<NBATCH * A_TILES, A_THREADS>>>(feats, out);

    cudaFuncSetAttribute(energy_kernel,
                         cudaFuncAttributeMaxDynamicSharedMemorySize, B_SMEM);
    energy_kernel<<<NBATCH * B_SPLIT, B_THREADS, B_SMEM>>>(
        bond_type, angle_type, tor_type, mult, opt_pars, out);
}